// round 2
// baseline (speedup 1.0000x reference)
#include <cuda_runtime.h>
#include <cuda_bf16.h>

#define B_    2
#define S_    2048
#define HID_  4096
#define NH_   32
#define NKV_  8
#define HD_   128
#define MROWS (B_ * S_)     // 4096
#define WIN_  1024

// Scratch (allocation-free: __device__ globals)
__device__ float g_Q[(size_t)MROWS * NH_ * HD_];    // 64 MB
__device__ float g_K[(size_t)MROWS * NKV_ * HD_];   // 16 MB
__device__ float g_V[(size_t)MROWS * NKV_ * HD_];   // 16 MB
__device__ float g_AO[(size_t)MROWS * NH_ * HD_];   // 64 MB

// ---------------------------------------------------------------------------
// SGEMM: C[M,N] = A[M,K] @ B[K,N], all row-major, dims multiples of tile sizes
// 128x128 tile, BK=16, 256 threads, 8x8 per thread.
// ---------------------------------------------------------------------------
#define BM 128
#define BN 128
#define BK 16
#define ASTRIDE 133   // padded to kill A-store bank conflicts

__global__ __launch_bounds__(256) void sgemm_kernel(
    const float* __restrict__ A, const float* __restrict__ Bw,
    float* __restrict__ C, int M, int N, int K)
{
    __shared__ float As[BK][ASTRIDE];
    __shared__ float Bs[BK][BN];

    const int t  = threadIdx.x;
    const int bm = blockIdx.y * BM;
    const int bn = blockIdx.x * BN;

    const int a_row = t >> 2;          // 0..63
    const int a_col = (t & 3) << 2;    // 0,4,8,12
    const int b_row = t >> 5;          // 0..7
    const int b_col = (t & 31) << 2;   // 0..124

    const int tx = t & 15;
    const int ty = t >> 4;

    const float* Ap  = A  + (size_t)(bm + a_row) * K + a_col;
    const float* Ap2 = Ap + (size_t)64 * K;
    const float* Bp  = Bw + (size_t)b_row * N + bn + b_col;
    const float* Bp2 = Bp + (size_t)8 * N;

    float acc[8][8];
    #pragma unroll
    for (int i = 0; i < 8; i++)
        #pragma unroll
        for (int j = 0; j < 8; j++) acc[i][j] = 0.f;

    for (int kt = 0; kt < K; kt += BK) {
        float4 a0 = *(const float4*)(Ap  + kt);
        float4 a1 = *(const float4*)(Ap2 + kt);
        float4 b0 = *(const float4*)(Bp  + (size_t)kt * N);
        float4 b1 = *(const float4*)(Bp2 + (size_t)kt * N);

        As[a_col + 0][a_row] = a0.x;
        As[a_col + 1][a_row] = a0.y;
        As[a_col + 2][a_row] = a0.z;
        As[a_col + 3][a_row] = a0.w;
        As[a_col + 0][a_row + 64] = a1.x;
        As[a_col + 1][a_row + 64] = a1.y;
        As[a_col + 2][a_row + 64] = a1.z;
        As[a_col + 3][a_row + 64] = a1.w;
        *(float4*)&Bs[b_row][b_col]     = b0;
        *(float4*)&Bs[b_row + 8][b_col] = b1;
        __syncthreads();

        #pragma unroll
        for (int k = 0; k < BK; k++) {
            float af[8], bf[8];
            #pragma unroll
            for (int i = 0; i < 8; i++) af[i] = As[k][ty * 8 + i];
            float4 bv0 = *(const float4*)&Bs[k][tx * 8];
            float4 bv1 = *(const float4*)&Bs[k][tx * 8 + 4];
            bf[0] = bv0.x; bf[1] = bv0.y; bf[2] = bv0.z; bf[3] = bv0.w;
            bf[4] = bv1.x; bf[5] = bv1.y; bf[6] = bv1.z; bf[7] = bv1.w;
            #pragma unroll
            for (int i = 0; i < 8; i++)
                #pragma unroll
                for (int j = 0; j < 8; j++)
                    acc[i][j] = fmaf(af[i], bf[j], acc[i][j]);
        }
        __syncthreads();
    }

    #pragma unroll
    for (int i = 0; i < 8; i++) {
        float* Cp = C + (size_t)(bm + ty * 8 + i) * N + bn + tx * 8;
        *(float4*)(Cp)     = make_float4(acc[i][0], acc[i][1], acc[i][2], acc[i][3]);
        *(float4*)(Cp + 4) = make_float4(acc[i][4], acc[i][5], acc[i][6], acc[i][7]);
    }
}

// ---------------------------------------------------------------------------
// RoPE (in-place on g_Q and g_K). One thread per rotation pair (t, t+64).
// ---------------------------------------------------------------------------
__global__ void rope_kernel(const int* __restrict__ pos_ids)
{
    const int QP = MROWS * NH_ * 64;    // 8388608
    const int KP = MROWS * NKV_ * 64;   // 2097152
    int idx = blockIdx.x * blockDim.x + threadIdx.x;
    if (idx >= QP + KP) return;

    float* base;
    int m, tt;
    if (idx < QP) {
        m = idx >> 11;                  // / (NH_*64)
        int r = idx & 2047;
        base = g_Q + ((size_t)m * NH_ + (r >> 6)) * HD_;
        tt = r & 63;
    } else {
        int i2 = idx - QP;
        m = i2 >> 9;                    // / (NKV_*64)
        int r = i2 & 511;
        base = g_K + ((size_t)m * NKV_ + (r >> 6)) * HD_;
        tt = r & 63;
    }
    float pos = (float)pos_ids[m];
    // inv_freq = 10000^(-t/64) = 2^(-t * log2(10000)/64)
    float inv = exp2f((float)tt * -0.20762050593045857f);
    float ang = pos * inv;
    float sv, cv;
    sincosf(ang, &sv, &cv);
    float x0 = base[tt];
    float x1 = base[tt + 64];
    base[tt]      = x0 * cv - x1 * sv;
    base[tt + 64] = x1 * cv + x0 * sv;
}

// ---------------------------------------------------------------------------
// Flash attention, sliding window 1024, GQA (4 Q heads per KV head).
// Block = (q_tile of 64, head, batch). 256 threads.
// Thread (g = t>>4, q = t&15): owns Q rows {g+16i}, score keys {q+16j},
// output cols {q*8 .. q*8+8}. Smem XOR-swizzled on col4 by (row&7).
// ---------------------------------------------------------------------------
__global__ __launch_bounds__(256) void attn_kernel()
{
    extern __shared__ float sm[];
    float* Qs = sm;             // [64][128] swizzled
    float* Ks = sm + 8192;      // [64][128] swizzled
    float* Vs = sm + 16384;     // [64][128] plain
    float* Ps = sm + 24576;     // [64][65]

    const int t     = threadIdx.x;
    const int qtile = blockIdx.x;
    const int h     = blockIdx.y;
    const int b     = blockIdx.z;
    const int q0    = qtile * 64;
    const int kvh   = h >> 2;

    const int g  = t >> 4;   // 0..15
    const int qq = t & 15;   // 0..15

    // ---- load Q tile (swizzled) ----
    {
        const float* Qg = g_Q + ((size_t)(b * S_ + q0) * NH_ + h) * HD_;
        #pragma unroll
        for (int it = 0; it < 8; it++) {
            int lf  = t + it * 256;
            int row = lf >> 5;
            int c4  = lf & 31;
            float4 v = *(const float4*)(Qg + (size_t)row * (NH_ * HD_) + (c4 << 2));
            *(float4*)&Qs[row * 128 + ((c4 ^ (row & 7)) << 2)] = v;
        }
    }

    float m_i[4], l_i[4], acc[4][8];
    #pragma unroll
    for (int i = 0; i < 4; i++) {
        m_i[i] = -1e30f;
        l_i[i] = 0.f;
        #pragma unroll
        for (int c = 0; c < 8; c++) acc[i][c] = 0.f;
    }

    const int kb_lo = (q0 >= WIN_) ? ((q0 - WIN_) >> 6) : 0;
    const int kb_hi = qtile;
    const float scale = 0.08838834764831845f;   // 1/sqrt(128)

    for (int kb = kb_lo; kb <= kb_hi; kb++) {
        __syncthreads();   // previous PV reads done before overwriting tiles
        {
            const float* Kg = g_K + ((size_t)(b * S_ + kb * 64) * NKV_ + kvh) * HD_;
            const float* Vg = g_V + ((size_t)(b * S_ + kb * 64) * NKV_ + kvh) * HD_;
            #pragma unroll
            for (int it = 0; it < 8; it++) {
                int lf  = t + it * 256;
                int row = lf >> 5;
                int c4  = lf & 31;
                size_t goff = (size_t)row * (NKV_ * HD_) + (c4 << 2);
                float4 kvv = *(const float4*)(Kg + goff);
                *(float4*)&Ks[row * 128 + ((c4 ^ (row & 7)) << 2)] = kvv;
                float4 vvv = *(const float4*)(Vg + goff);
                *(float4*)&Vs[row * 128 + (c4 << 2)] = vvv;
            }
        }
        __syncthreads();

        // ---- scores: 4 rows x 4 keys per thread ----
        float s[4][4];
        #pragma unroll
        for (int i = 0; i < 4; i++)
            #pragma unroll
            for (int j = 0; j < 4; j++) s[i][j] = 0.f;

        const int qsw = g & 7;    // (g+16i)&7 is invariant in i
        const int ksw = qq & 7;
        #pragma unroll 4
        for (int d4 = 0; d4 < 32; d4++) {
            float4 qv[4], kv[4];
            int qoff = (d4 ^ qsw) << 2;
            int koff = (d4 ^ ksw) << 2;
            #pragma unroll
            for (int i = 0; i < 4; i++)
                qv[i] = *(const float4*)&Qs[(g + 16 * i) * 128 + qoff];
            #pragma unroll
            for (int j = 0; j < 4; j++)
                kv[j] = *(const float4*)&Ks[(qq + 16 * j) * 128 + koff];
            #pragma unroll
            for (int i = 0; i < 4; i++)
                #pragma unroll
                for (int j = 0; j < 4; j++)
                    s[i][j] += qv[i].x * kv[j].x + qv[i].y * kv[j].y
                             + qv[i].z * kv[j].z + qv[i].w * kv[j].w;
        }

        // ---- scale + sliding-window causal mask + row max ----
        float rmax[4];
        #pragma unroll
        for (int i = 0; i < 4; i++) {
            int gi = q0 + g + 16 * i;
            float mx = -1e30f;
            #pragma unroll
            for (int j = 0; j < 4; j++) {
                int gj = kb * 64 + qq + 16 * j;
                float sv = s[i][j] * scale;
                sv = (gj <= gi && gj + WIN_ >= gi) ? sv : -1e30f;
                s[i][j] = sv;
                mx = fmaxf(mx, sv);
            }
            rmax[i] = mx;
        }
        #pragma unroll
        for (int off = 1; off < 16; off <<= 1)
            #pragma unroll
            for (int i = 0; i < 4; i++)
                rmax[i] = fmaxf(rmax[i], __shfl_xor_sync(0xffffffffu, rmax[i], off));

        // ---- online softmax update ----
        float rs[4];
        #pragma unroll
        for (int i = 0; i < 4; i++) {
            float mnew  = fmaxf(m_i[i], rmax[i]);
            float alpha = __expf(m_i[i] - mnew);
            m_i[i] = mnew;
            float ssum = 0.f;
            #pragma unroll
            for (int j = 0; j < 4; j++) {
                float p = __expf(s[i][j] - mnew);
                Ps[(g + 16 * i) * 65 + qq + 16 * j] = p;
                ssum += p;
            }
            rs[i]  = ssum;
            l_i[i] = l_i[i] * alpha;
            #pragma unroll
            for (int c = 0; c < 8; c++) acc[i][c] *= alpha;
        }
        #pragma unroll
        for (int off = 1; off < 16; off <<= 1)
            #pragma unroll
            for (int i = 0; i < 4; i++)
                rs[i] += __shfl_xor_sync(0xffffffffu, rs[i], off);
        #pragma unroll
        for (int i = 0; i < 4; i++) l_i[i] += rs[i];

        __syncthreads();   // Ps visible to all

        // ---- PV: acc[4 rows][8 cols] ----
        #pragma unroll 4
        for (int j = 0; j < 64; j++) {
            float pv[4];
            #pragma unroll
            for (int i = 0; i < 4; i++) pv[i] = Ps[(g + 16 * i) * 65 + j];
            float4 v0 = *(const float4*)&Vs[j * 128 + qq * 8];
            float4 v1 = *(const float4*)&Vs[j * 128 + qq * 8 + 4];
            #pragma unroll
            for (int i = 0; i < 4; i++) {
                acc[i][0] = fmaf(pv[i], v0.x, acc[i][0]);
                acc[i][1] = fmaf(pv[i], v0.y, acc[i][1]);
                acc[i][2] = fmaf(pv[i], v0.z, acc[i][2]);
                acc[i][3] = fmaf(pv[i], v0.w, acc[i][3]);
                acc[i][4] = fmaf(pv[i], v1.x, acc[i][4]);
                acc[i][5] = fmaf(pv[i], v1.y, acc[i][5]);
                acc[i][6] = fmaf(pv[i], v1.z, acc[i][6]);
                acc[i][7] = fmaf(pv[i], v1.w, acc[i][7]);
            }
        }
    }

    // ---- epilogue: normalize and store to g_AO [M][NH*HD] ----
    #pragma unroll
    for (int i = 0; i < 4; i++) {
        float inv = 1.f / l_i[i];
        int row = q0 + g + 16 * i;
        float* op = g_AO + (size_t)(b * S_ + row) * (NH_ * HD_) + h * HD_ + qq * 8;
        *(float4*)op       = make_float4(acc[i][0] * inv, acc[i][1] * inv,
                                         acc[i][2] * inv, acc[i][3] * inv);
        *(float4*)(op + 4) = make_float4(acc[i][4] * inv, acc[i][5] * inv,
                                         acc[i][6] * inv, acc[i][7] * inv);
    }
}

// ---------------------------------------------------------------------------
extern "C" void kernel_launch(void* const* d_in, const int* in_sizes, int n_in,
                              void* d_out, int out_size)
{
    (void)in_sizes; (void)n_in; (void)out_size;
    const float* hidden  = (const float*)d_in[0];
    // d_in[1] = attention_mask (all ones in this problem; band mask handles causality)
    const int*   pos_ids = (const int*)d_in[2];
    const float* q_w     = (const float*)d_in[3];
    const float* k_w     = (const float*)d_in[4];
    const float* v_w     = (const float*)d_in[5];
    const float* o_w     = (const float*)d_in[6];
    float* out = (float*)d_out;

    float *Qd, *Kd, *Vd, *AOd;
    cudaGetSymbolAddress((void**)&Qd,  g_Q);
    cudaGetSymbolAddress((void**)&Kd,  g_K);
    cudaGetSymbolAddress((void**)&Vd,  g_V);
    cudaGetSymbolAddress((void**)&AOd, g_AO);

    // QKV projections
    sgemm_kernel<<<dim3(NH_ * HD_ / BN, MROWS / BM), 256>>>(hidden, q_w, Qd, MROWS, NH_ * HD_, HID_);
    sgemm_kernel<<<dim3(NKV_ * HD_ / BN, MROWS / BM), 256>>>(hidden, k_w, Kd, MROWS, NKV_ * HD_, HID_);
    sgemm_kernel<<<dim3(NKV_ * HD_ / BN, MROWS / BM), 256>>>(hidden, v_w, Vd, MROWS, NKV_ * HD_, HID_);

    // RoPE
    {
        int total = MROWS * NH_ * 64 + MROWS * NKV_ * 64;
        rope_kernel<<<(total + 255) / 256, 256>>>(pos_ids);
    }

    // Attention
    {
        int smem = (3 * 64 * 128 + 64 * 65) * (int)sizeof(float);  // 114944 B
        static int attr_set = 0;
        cudaFuncSetAttribute(attn_kernel, cudaFuncAttributeMaxDynamicSharedMemorySize, smem);
        (void)attr_set;
        attn_kernel<<<dim3(S_ / 64, NH_, B_), 256, smem>>>();
    }

    // Output projection
    sgemm_kernel<<<dim3(HID_ / BN, MROWS / BM), 256>>>(AOd, o_w, out, MROWS, HID_, HID_);
}

// round 3
// speedup vs baseline: 2.1634x; 2.1634x over previous
#include <cuda_runtime.h>
#include <cuda_bf16.h>

#define B_    2
#define S_    2048
#define HID_  4096
#define NH_   32
#define NKV_  8
#define HD_   128
#define MROWS (B_ * S_)     // 4096
#define WIN_  1024

// Scratch (allocation-free: __device__ globals)
__device__ float g_Q[(size_t)MROWS * NH_ * HD_];    // 64 MB
__device__ float g_K[(size_t)MROWS * NKV_ * HD_];   // 16 MB
__device__ float g_V[(size_t)MROWS * NKV_ * HD_];   // 16 MB
__device__ float g_AO[(size_t)MROWS * NH_ * HD_];   // 64 MB

// ---------------------------------------------------------------------------
// TF32 tensor-core GEMM: C[M,N] = A[M,K] @ B[K,N], row-major.
// 128x128x32 block tile, 256 threads (8 warps), warp tile 64x32 via
// mma.sync.m16n8k8.tf32 (4 m-tiles x 4 n-tiles x 4 k-steps).
// Inputs rounded to tf32 with cvt.rna at STS (unbiased; truncation would
// accumulate a coherent ~1e-3 deficit over K=4096).
// ---------------------------------------------------------------------------
#define TFBM 128
#define TFBN 128
#define TFBK 32
#define ASTR 36    // A smem [m][k] row stride (pad 4): frag banks == lane id
#define BSTR 136   // B smem [k][n] row stride (pad 8): frag banks == lane id
#define ASZ (TFBM * ASTR)   // 4608 floats
#define BSZ (TFBK * BSTR)   // 4352 floats

__device__ __forceinline__ float f2tf32(float x) {
    unsigned r;
    asm("cvt.rna.tf32.f32 %0, %1;" : "=r"(r) : "f"(x));
    return __uint_as_float(r);
}

__device__ __forceinline__ void mma_tf32(
    float* c, unsigned a0, unsigned a1, unsigned a2, unsigned a3,
    unsigned b0, unsigned b1)
{
    asm volatile(
        "mma.sync.aligned.m16n8k8.row.col.f32.tf32.tf32.f32 "
        "{%0,%1,%2,%3}, {%4,%5,%6,%7}, {%8,%9}, {%0,%1,%2,%3};\n"
        : "+f"(c[0]), "+f"(c[1]), "+f"(c[2]), "+f"(c[3])
        : "r"(a0), "r"(a1), "r"(a2), "r"(a3), "r"(b0), "r"(b1));
}

__global__ __launch_bounds__(256) void tf32_gemm(
    const float* __restrict__ A, const float* __restrict__ Bw,
    float* __restrict__ C, int M, int N, int K)
{
    extern __shared__ float sh[];
    float* As = sh;                // 2 x ASZ
    float* Bs = sh + 2 * ASZ;      // 2 x BSZ

    const int t    = threadIdx.x;
    const int warp = t >> 5;
    const int lane = t & 31;
    const int wm   = (warp >> 2) * 64;   // warp row offset in tile
    const int wn   = (warp & 3) * 32;    // warp col offset in tile
    const int bm   = blockIdx.y * TFBM;
    const int bn   = blockIdx.x * TFBN;

    // global load mapping
    const int arow = t >> 3;            // 0..31, +i*32
    const int acol = (t & 7) << 2;      // 0..28
    const int brow = t >> 5;            // 0..7, +i*8
    const int bcol = (t & 31) << 2;     // 0..124

    const float* Ag = A  + (size_t)(bm + arow) * K + acol;
    const float* Bg = Bw + (size_t)brow * N + bn + bcol;

    float4 ra[4], rb[4];

    const int NKT = K / TFBK;

    // prefetch chunk 0
    #pragma unroll
    for (int i = 0; i < 4; i++) ra[i] = *(const float4*)(Ag + (size_t)(i * 32) * K);
    #pragma unroll
    for (int i = 0; i < 4; i++) rb[i] = *(const float4*)(Bg + (size_t)(i * 8) * N);

    // STS chunk 0 (with tf32 rounding)
    #pragma unroll
    for (int i = 0; i < 4; i++) {
        float* p = As + (arow + i * 32) * ASTR + acol;
        p[0] = f2tf32(ra[i].x); p[1] = f2tf32(ra[i].y);
        p[2] = f2tf32(ra[i].z); p[3] = f2tf32(ra[i].w);
    }
    #pragma unroll
    for (int i = 0; i < 4; i++) {
        float* p = Bs + (brow + i * 8) * BSTR + bcol;
        p[0] = f2tf32(rb[i].x); p[1] = f2tf32(rb[i].y);
        p[2] = f2tf32(rb[i].z); p[3] = f2tf32(rb[i].w);
    }
    __syncthreads();

    float acc[4][4][4];
    #pragma unroll
    for (int mt = 0; mt < 4; mt++)
        #pragma unroll
        for (int nt = 0; nt < 4; nt++)
            #pragma unroll
            for (int c = 0; c < 4; c++) acc[mt][nt][c] = 0.f;

    const int frag_m = lane >> 2;   // 0..7
    const int frag_k = lane & 3;    // 0..3

    for (int kt = 0; kt < NKT; kt++) {
        // prefetch next chunk into registers
        if (kt + 1 < NKT) {
            const float* Agn = Ag + (size_t)(kt + 1) * TFBK;
            const float* Bgn = Bg + (size_t)(kt + 1) * TFBK * N;
            #pragma unroll
            for (int i = 0; i < 4; i++) ra[i] = *(const float4*)(Agn + (size_t)(i * 32) * K);
            #pragma unroll
            for (int i = 0; i < 4; i++) rb[i] = *(const float4*)(Bgn + (size_t)(i * 8) * N);
        }

        const float* Ab = As + (kt & 1) * ASZ;
        const float* Bb = Bs + (kt & 1) * BSZ;

        #pragma unroll
        for (int ks = 0; ks < 4; ks++) {
            const int k = ks * 8 + frag_k;
            unsigned af[4][4], bf[4][2];
            #pragma unroll
            for (int mt = 0; mt < 4; mt++) {
                const float* p = Ab + (wm + mt * 16 + frag_m) * ASTR + k;
                af[mt][0] = __float_as_uint(p[0]);
                af[mt][1] = __float_as_uint(p[8 * ASTR]);
                af[mt][2] = __float_as_uint(p[4]);
                af[mt][3] = __float_as_uint(p[8 * ASTR + 4]);
            }
            #pragma unroll
            for (int nt = 0; nt < 4; nt++) {
                const float* p = Bb + k * BSTR + wn + nt * 8 + frag_m;
                bf[nt][0] = __float_as_uint(p[0]);
                bf[nt][1] = __float_as_uint(p[4 * BSTR]);
            }
            #pragma unroll
            for (int mt = 0; mt < 4; mt++)
                #pragma unroll
                for (int nt = 0; nt < 4; nt++)
                    mma_tf32(acc[mt][nt], af[mt][0], af[mt][1], af[mt][2], af[mt][3],
                             bf[nt][0], bf[nt][1]);
        }

        // STS next chunk into the other buffer
        if (kt + 1 < NKT) {
            float* Abn = As + ((kt + 1) & 1) * ASZ;
            float* Bbn = Bs + ((kt + 1) & 1) * BSZ;
            #pragma unroll
            for (int i = 0; i < 4; i++) {
                float* p = Abn + (arow + i * 32) * ASTR + acol;
                p[0] = f2tf32(ra[i].x); p[1] = f2tf32(ra[i].y);
                p[2] = f2tf32(ra[i].z); p[3] = f2tf32(ra[i].w);
            }
            #pragma unroll
            for (int i = 0; i < 4; i++) {
                float* p = Bbn + (brow + i * 8) * BSTR + bcol;
                p[0] = f2tf32(rb[i].x); p[1] = f2tf32(rb[i].y);
                p[2] = f2tf32(rb[i].z); p[3] = f2tf32(rb[i].w);
            }
        }
        __syncthreads();
    }

    // epilogue
    #pragma unroll
    for (int mt = 0; mt < 4; mt++) {
        const int row0 = bm + wm + mt * 16 + frag_m;
        #pragma unroll
        for (int nt = 0; nt < 4; nt++) {
            const int col = bn + wn + nt * 8 + (frag_k << 1);
            *(float2*)(C + (size_t)row0 * N + col) =
                make_float2(acc[mt][nt][0], acc[mt][nt][1]);
            *(float2*)(C + (size_t)(row0 + 8) * N + col) =
                make_float2(acc[mt][nt][2], acc[mt][nt][3]);
        }
    }
}

// ---------------------------------------------------------------------------
// RoPE (in-place on g_Q and g_K). One thread per rotation pair (t, t+64).
// ---------------------------------------------------------------------------
__global__ void rope_kernel(const int* __restrict__ pos_ids)
{
    const int QP = MROWS * NH_ * 64;    // 8388608
    const int KP = MROWS * NKV_ * 64;   // 2097152
    int idx = blockIdx.x * blockDim.x + threadIdx.x;
    if (idx >= QP + KP) return;

    float* base;
    int m, tt;
    if (idx < QP) {
        m = idx >> 11;
        int r = idx & 2047;
        base = g_Q + ((size_t)m * NH_ + (r >> 6)) * HD_;
        tt = r & 63;
    } else {
        int i2 = idx - QP;
        m = i2 >> 9;
        int r = i2 & 511;
        base = g_K + ((size_t)m * NKV_ + (r >> 6)) * HD_;
        tt = r & 63;
    }
    float pos = (float)pos_ids[m];
    float inv = exp2f((float)tt * -0.20762050593045857f);
    float ang = pos * inv;
    float sv, cv;
    sincosf(ang, &sv, &cv);
    float x0 = base[tt];
    float x1 = base[tt + 64];
    base[tt]      = x0 * cv - x1 * sv;
    base[tt + 64] = x1 * cv + x0 * sv;
}

// ---------------------------------------------------------------------------
// Flash attention, sliding window 1024, GQA (4 Q heads per KV head).
// Block = (q_tile of 64, head, batch). 256 threads. SIMT fp32.
// ---------------------------------------------------------------------------
__global__ __launch_bounds__(256) void attn_kernel()
{
    extern __shared__ float sm[];
    float* Qs = sm;             // [64][128] swizzled
    float* Ks = sm + 8192;      // [64][128] swizzled
    float* Vs = sm + 16384;     // [64][128] plain
    float* Ps = sm + 24576;     // [64][65]

    const int t     = threadIdx.x;
    const int qtile = blockIdx.x;
    const int h     = blockIdx.y;
    const int b     = blockIdx.z;
    const int q0    = qtile * 64;
    const int kvh   = h >> 2;

    const int g  = t >> 4;   // 0..15
    const int qq = t & 15;   // 0..15

    {
        const float* Qg = g_Q + ((size_t)(b * S_ + q0) * NH_ + h) * HD_;
        #pragma unroll
        for (int it = 0; it < 8; it++) {
            int lf  = t + it * 256;
            int row = lf >> 5;
            int c4  = lf & 31;
            float4 v = *(const float4*)(Qg + (size_t)row * (NH_ * HD_) + (c4 << 2));
            *(float4*)&Qs[row * 128 + ((c4 ^ (row & 7)) << 2)] = v;
        }
    }

    float m_i[4], l_i[4], acc[4][8];
    #pragma unroll
    for (int i = 0; i < 4; i++) {
        m_i[i] = -1e30f;
        l_i[i] = 0.f;
        #pragma unroll
        for (int c = 0; c < 8; c++) acc[i][c] = 0.f;
    }

    const int kb_lo = (q0 >= WIN_) ? ((q0 - WIN_) >> 6) : 0;
    const int kb_hi = qtile;
    const float scale = 0.08838834764831845f;

    for (int kb = kb_lo; kb <= kb_hi; kb++) {
        __syncthreads();
        {
            const float* Kg = g_K + ((size_t)(b * S_ + kb * 64) * NKV_ + kvh) * HD_;
            const float* Vg = g_V + ((size_t)(b * S_ + kb * 64) * NKV_ + kvh) * HD_;
            #pragma unroll
            for (int it = 0; it < 8; it++) {
                int lf  = t + it * 256;
                int row = lf >> 5;
                int c4  = lf & 31;
                size_t goff = (size_t)row * (NKV_ * HD_) + (c4 << 2);
                float4 kvv = *(const float4*)(Kg + goff);
                *(float4*)&Ks[row * 128 + ((c4 ^ (row & 7)) << 2)] = kvv;
                float4 vvv = *(const float4*)(Vg + goff);
                *(float4*)&Vs[row * 128 + (c4 << 2)] = vvv;
            }
        }
        __syncthreads();

        float s[4][4];
        #pragma unroll
        for (int i = 0; i < 4; i++)
            #pragma unroll
            for (int j = 0; j < 4; j++) s[i][j] = 0.f;

        const int qsw = g & 7;
        const int ksw = qq & 7;
        #pragma unroll 4
        for (int d4 = 0; d4 < 32; d4++) {
            float4 qv[4], kv[4];
            int qoff = (d4 ^ qsw) << 2;
            int koff = (d4 ^ ksw) << 2;
            #pragma unroll
            for (int i = 0; i < 4; i++)
                qv[i] = *(const float4*)&Qs[(g + 16 * i) * 128 + qoff];
            #pragma unroll
            for (int j = 0; j < 4; j++)
                kv[j] = *(const float4*)&Ks[(qq + 16 * j) * 128 + koff];
            #pragma unroll
            for (int i = 0; i < 4; i++)
                #pragma unroll
                for (int j = 0; j < 4; j++)
                    s[i][j] += qv[i].x * kv[j].x + qv[i].y * kv[j].y
                             + qv[i].z * kv[j].z + qv[i].w * kv[j].w;
        }

        float rmax[4];
        #pragma unroll
        for (int i = 0; i < 4; i++) {
            int gi = q0 + g + 16 * i;
            float mx = -1e30f;
            #pragma unroll
            for (int j = 0; j < 4; j++) {
                int gj = kb * 64 + qq + 16 * j;
                float sv = s[i][j] * scale;
                sv = (gj <= gi && gj + WIN_ >= gi) ? sv : -1e30f;
                s[i][j] = sv;
                mx = fmaxf(mx, sv);
            }
            rmax[i] = mx;
        }
        #pragma unroll
        for (int off = 1; off < 16; off <<= 1)
            #pragma unroll
            for (int i = 0; i < 4; i++)
                rmax[i] = fmaxf(rmax[i], __shfl_xor_sync(0xffffffffu, rmax[i], off));

        float rs[4];
        #pragma unroll
        for (int i = 0; i < 4; i++) {
            float mnew  = fmaxf(m_i[i], rmax[i]);
            float alpha = __expf(m_i[i] - mnew);
            m_i[i] = mnew;
            float ssum = 0.f;
            #pragma unroll
            for (int j = 0; j < 4; j++) {
                float p = __expf(s[i][j] - mnew);
                Ps[(g + 16 * i) * 65 + qq + 16 * j] = p;
                ssum += p;
            }
            rs[i]  = ssum;
            l_i[i] = l_i[i] * alpha;
            #pragma unroll
            for (int c = 0; c < 8; c++) acc[i][c] *= alpha;
        }
        #pragma unroll
        for (int off = 1; off < 16; off <<= 1)
            #pragma unroll
            for (int i = 0; i < 4; i++)
                rs[i] += __shfl_xor_sync(0xffffffffu, rs[i], off);
        #pragma unroll
        for (int i = 0; i < 4; i++) l_i[i] += rs[i];

        __syncthreads();

        #pragma unroll 4
        for (int j = 0; j < 64; j++) {
            float pv[4];
            #pragma unroll
            for (int i = 0; i < 4; i++) pv[i] = Ps[(g + 16 * i) * 65 + j];
            float4 v0 = *(const float4*)&Vs[j * 128 + qq * 8];
            float4 v1 = *(const float4*)&Vs[j * 128 + qq * 8 + 4];
            #pragma unroll
            for (int i = 0; i < 4; i++) {
                acc[i][0] = fmaf(pv[i], v0.x, acc[i][0]);
                acc[i][1] = fmaf(pv[i], v0.y, acc[i][1]);
                acc[i][2] = fmaf(pv[i], v0.z, acc[i][2]);
                acc[i][3] = fmaf(pv[i], v0.w, acc[i][3]);
                acc[i][4] = fmaf(pv[i], v1.x, acc[i][4]);
                acc[i][5] = fmaf(pv[i], v1.y, acc[i][5]);
                acc[i][6] = fmaf(pv[i], v1.z, acc[i][6]);
                acc[i][7] = fmaf(pv[i], v1.w, acc[i][7]);
            }
        }
    }

    #pragma unroll
    for (int i = 0; i < 4; i++) {
        float inv = 1.f / l_i[i];
        int row = q0 + g + 16 * i;
        float* op = g_AO + (size_t)(b * S_ + row) * (NH_ * HD_) + h * HD_ + qq * 8;
        *(float4*)op       = make_float4(acc[i][0] * inv, acc[i][1] * inv,
                                         acc[i][2] * inv, acc[i][3] * inv);
        *(float4*)(op + 4) = make_float4(acc[i][4] * inv, acc[i][5] * inv,
                                         acc[i][6] * inv, acc[i][7] * inv);
    }
}

// ---------------------------------------------------------------------------
extern "C" void kernel_launch(void* const* d_in, const int* in_sizes, int n_in,
                              void* d_out, int out_size)
{
    (void)in_sizes; (void)n_in; (void)out_size;
    const float* hidden  = (const float*)d_in[0];
    const int*   pos_ids = (const int*)d_in[2];
    const float* q_w     = (const float*)d_in[3];
    const float* k_w     = (const float*)d_in[4];
    const float* v_w     = (const float*)d_in[5];
    const float* o_w     = (const float*)d_in[6];
    float* out = (float*)d_out;

    float *Qd, *Kd, *Vd, *AOd;
    cudaGetSymbolAddress((void**)&Qd,  g_Q);
    cudaGetSymbolAddress((void**)&Kd,  g_K);
    cudaGetSymbolAddress((void**)&Vd,  g_V);
    cudaGetSymbolAddress((void**)&AOd, g_AO);

    const int gemm_smem = 2 * (ASZ + BSZ) * (int)sizeof(float);  // 71680
    cudaFuncSetAttribute(tf32_gemm, cudaFuncAttributeMaxDynamicSharedMemorySize, gemm_smem);

    // QKV projections (tensor cores, tf32)
    tf32_gemm<<<dim3(NH_ * HD_ / TFBN, MROWS / TFBM), 256, gemm_smem>>>(
        hidden, q_w, Qd, MROWS, NH_ * HD_, HID_);
    tf32_gemm<<<dim3(NKV_ * HD_ / TFBN, MROWS / TFBM), 256, gemm_smem>>>(
        hidden, k_w, Kd, MROWS, NKV_ * HD_, HID_);
    tf32_gemm<<<dim3(NKV_ * HD_ / TFBN, MROWS / TFBM), 256, gemm_smem>>>(
        hidden, v_w, Vd, MROWS, NKV_ * HD_, HID_);

    // RoPE
    {
        int total = MROWS * NH_ * 64 + MROWS * NKV_ * 64;
        rope_kernel<<<(total + 255) / 256, 256>>>(pos_ids);
    }

    // Attention
    {
        int smem = (3 * 64 * 128 + 64 * 65) * (int)sizeof(float);  // 114944 B
        cudaFuncSetAttribute(attn_kernel, cudaFuncAttributeMaxDynamicSharedMemorySize, smem);
        attn_kernel<<<dim3(S_ / 64, NH_, B_), 256, smem>>>();
    }

    // Output projection
    tf32_gemm<<<dim3(HID_ / TFBN, MROWS / TFBM), 256, gemm_smem>>>(
        AOd, o_w, out, MROWS, HID_, HID_);
}

// round 4
// speedup vs baseline: 2.6902x; 1.2435x over previous
#include <cuda_runtime.h>
#include <cuda_bf16.h>

#define B_    2
#define S_    2048
#define HID_  4096
#define NH_   32
#define NKV_  8
#define HD_   128
#define MROWS (B_ * S_)     // 4096
#define WIN_  1024

// Scratch (allocation-free: __device__ globals)
__device__ float g_Q[(size_t)MROWS * NH_ * HD_];    // 64 MB
__device__ float g_K[(size_t)MROWS * NKV_ * HD_];   // 16 MB
__device__ float g_V[(size_t)MROWS * NKV_ * HD_];   // 16 MB
__device__ float g_AO[(size_t)MROWS * NH_ * HD_];   // 64 MB

__device__ __forceinline__ float f2tf32(float x) {
    unsigned r;
    asm("cvt.rna.tf32.f32 %0, %1;" : "=r"(r) : "f"(x));
    return __uint_as_float(r);
}

__device__ __forceinline__ void mma_tf32(
    float* c, unsigned a0, unsigned a1, unsigned a2, unsigned a3,
    unsigned b0, unsigned b1)
{
    asm volatile(
        "mma.sync.aligned.m16n8k8.row.col.f32.tf32.tf32.f32 "
        "{%0,%1,%2,%3}, {%4,%5,%6,%7}, {%8,%9}, {%0,%1,%2,%3};\n"
        : "+f"(c[0]), "+f"(c[1]), "+f"(c[2]), "+f"(c[3])
        : "r"(a0), "r"(a1), "r"(a2), "r"(a3), "r"(b0), "r"(b1));
}

// ---------------------------------------------------------------------------
// TF32 tensor-core GEMM: C[M,N] = A[M,K] @ B[K,N], row-major.
// 128x128x32 block tile, 256 threads (8 warps), warp tile 64x32.
// ---------------------------------------------------------------------------
#define TFBM 128
#define TFBN 128
#define TFBK 32
#define ASTR 36
#define BSTR 136
#define ASZ (TFBM * ASTR)
#define BSZ (TFBK * BSTR)

__global__ __launch_bounds__(256) void tf32_gemm(
    const float* __restrict__ A, const float* __restrict__ Bw,
    float* __restrict__ C, int M, int N, int K)
{
    extern __shared__ float sh[];
    float* As = sh;
    float* Bs = sh + 2 * ASZ;

    const int t    = threadIdx.x;
    const int warp = t >> 5;
    const int lane = t & 31;
    const int wm   = (warp >> 2) * 64;
    const int wn   = (warp & 3) * 32;
    const int bm   = blockIdx.y * TFBM;
    const int bn   = blockIdx.x * TFBN;

    const int arow = t >> 3;
    const int acol = (t & 7) << 2;
    const int brow = t >> 5;
    const int bcol = (t & 31) << 2;

    const float* Ag = A  + (size_t)(bm + arow) * K + acol;
    const float* Bg = Bw + (size_t)brow * N + bn + bcol;

    float4 ra[4], rb[4];
    const int NKT = K / TFBK;

    #pragma unroll
    for (int i = 0; i < 4; i++) ra[i] = *(const float4*)(Ag + (size_t)(i * 32) * K);
    #pragma unroll
    for (int i = 0; i < 4; i++) rb[i] = *(const float4*)(Bg + (size_t)(i * 8) * N);

    #pragma unroll
    for (int i = 0; i < 4; i++) {
        float* p = As + (arow + i * 32) * ASTR + acol;
        p[0] = f2tf32(ra[i].x); p[1] = f2tf32(ra[i].y);
        p[2] = f2tf32(ra[i].z); p[3] = f2tf32(ra[i].w);
    }
    #pragma unroll
    for (int i = 0; i < 4; i++) {
        float* p = Bs + (brow + i * 8) * BSTR + bcol;
        p[0] = f2tf32(rb[i].x); p[1] = f2tf32(rb[i].y);
        p[2] = f2tf32(rb[i].z); p[3] = f2tf32(rb[i].w);
    }
    __syncthreads();

    float acc[4][4][4];
    #pragma unroll
    for (int mt = 0; mt < 4; mt++)
        #pragma unroll
        for (int nt = 0; nt < 4; nt++)
            #pragma unroll
            for (int c = 0; c < 4; c++) acc[mt][nt][c] = 0.f;

    const int frag_m = lane >> 2;
    const int frag_k = lane & 3;

    for (int kt = 0; kt < NKT; kt++) {
        if (kt + 1 < NKT) {
            const float* Agn = Ag + (size_t)(kt + 1) * TFBK;
            const float* Bgn = Bg + (size_t)(kt + 1) * TFBK * N;
            #pragma unroll
            for (int i = 0; i < 4; i++) ra[i] = *(const float4*)(Agn + (size_t)(i * 32) * K);
            #pragma unroll
            for (int i = 0; i < 4; i++) rb[i] = *(const float4*)(Bgn + (size_t)(i * 8) * N);
        }

        const float* Ab = As + (kt & 1) * ASZ;
        const float* Bb = Bs + (kt & 1) * BSZ;

        #pragma unroll
        for (int ks = 0; ks < 4; ks++) {
            const int k = ks * 8 + frag_k;
            unsigned af[4][4], bf[4][2];
            #pragma unroll
            for (int mt = 0; mt < 4; mt++) {
                const float* p = Ab + (wm + mt * 16 + frag_m) * ASTR + k;
                af[mt][0] = __float_as_uint(p[0]);
                af[mt][1] = __float_as_uint(p[8 * ASTR]);
                af[mt][2] = __float_as_uint(p[4]);
                af[mt][3] = __float_as_uint(p[8 * ASTR + 4]);
            }
            #pragma unroll
            for (int nt = 0; nt < 4; nt++) {
                const float* p = Bb + k * BSTR + wn + nt * 8 + frag_m;
                bf[nt][0] = __float_as_uint(p[0]);
                bf[nt][1] = __float_as_uint(p[4 * BSTR]);
            }
            #pragma unroll
            for (int mt = 0; mt < 4; mt++)
                #pragma unroll
                for (int nt = 0; nt < 4; nt++)
                    mma_tf32(acc[mt][nt], af[mt][0], af[mt][1], af[mt][2], af[mt][3],
                             bf[nt][0], bf[nt][1]);
        }

        if (kt + 1 < NKT) {
            float* Abn = As + ((kt + 1) & 1) * ASZ;
            float* Bbn = Bs + ((kt + 1) & 1) * BSZ;
            #pragma unroll
            for (int i = 0; i < 4; i++) {
                float* p = Abn + (arow + i * 32) * ASTR + acol;
                p[0] = f2tf32(ra[i].x); p[1] = f2tf32(ra[i].y);
                p[2] = f2tf32(ra[i].z); p[3] = f2tf32(ra[i].w);
            }
            #pragma unroll
            for (int i = 0; i < 4; i++) {
                float* p = Bbn + (brow + i * 8) * BSTR + bcol;
                p[0] = f2tf32(rb[i].x); p[1] = f2tf32(rb[i].y);
                p[2] = f2tf32(rb[i].z); p[3] = f2tf32(rb[i].w);
            }
        }
        __syncthreads();
    }

    #pragma unroll
    for (int mt = 0; mt < 4; mt++) {
        const int row0 = bm + wm + mt * 16 + frag_m;
        #pragma unroll
        for (int nt = 0; nt < 4; nt++) {
            const int col = bn + wn + nt * 8 + (frag_k << 1);
            *(float2*)(C + (size_t)row0 * N + col) =
                make_float2(acc[mt][nt][0], acc[mt][nt][1]);
            *(float2*)(C + (size_t)(row0 + 8) * N + col) =
                make_float2(acc[mt][nt][2], acc[mt][nt][3]);
        }
    }
}

// ---------------------------------------------------------------------------
// RoPE (in-place on g_Q and g_K).
// ---------------------------------------------------------------------------
__global__ void rope_kernel(const int* __restrict__ pos_ids)
{
    const int QP = MROWS * NH_ * 64;
    const int KP = MROWS * NKV_ * 64;
    int idx = blockIdx.x * blockDim.x + threadIdx.x;
    if (idx >= QP + KP) return;

    float* base;
    int m, tt;
    if (idx < QP) {
        m = idx >> 11;
        int r = idx & 2047;
        base = g_Q + ((size_t)m * NH_ + (r >> 6)) * HD_;
        tt = r & 63;
    } else {
        int i2 = idx - QP;
        m = i2 >> 9;
        int r = i2 & 511;
        base = g_K + ((size_t)m * NKV_ + (r >> 6)) * HD_;
        tt = r & 63;
    }
    float pos = (float)pos_ids[m];
    float inv = exp2f((float)tt * -0.20762050593045857f);
    float ang = pos * inv;
    float sv, cv;
    sincosf(ang, &sv, &cv);
    float x0 = base[tt];
    float x1 = base[tt + 64];
    base[tt]      = x0 * cv - x1 * sv;
    base[tt + 64] = x1 * cv + x0 * sv;
}

// ---------------------------------------------------------------------------
// Tensor-core flash attention (tf32 mma), sliding window 1024, GQA.
// Block = (q_tile of 64, head, batch), 128 threads (4 warps x 16 q-rows).
// Smem strides chosen for conflict-free MMA fragment LDS:
//   Qs/Ks stride 132 -> bank = lane ; Vs stride 136 -> bank = lane-perm ;
//   Ps (per-warp) stride 68 -> A-frag loads bank = lane.
// ---------------------------------------------------------------------------
#define QSTR 132
#define KSTR 132
#define VSTR 136
#define PSTR 68

__global__ __launch_bounds__(128) void attn_mma_kernel()
{
    extern __shared__ float sm[];
    float* Qs = sm;                     // 64*132 = 8448
    float* Ks = sm + 8448;              // 8448
    float* Vs = sm + 16896;             // 64*136 = 8704
    float* Ps = sm + 25600;             // 4 warps * 16*68 = 4352
    // total 29952 floats = 119808 B

    const int t     = threadIdx.x;
    const int w     = t >> 5;
    const int lane  = t & 31;
    const int r     = lane >> 2;     // 0..7
    const int c     = lane & 3;      // 0..3
    const int qtile = (int)gridDim.x - 1 - (int)blockIdx.x;  // heavy tiles first
    const int h     = blockIdx.y;
    const int b     = blockIdx.z;
    const int q0    = qtile * 64;
    const int kvh   = h >> 2;

    float* Psw = Ps + w * (16 * PSTR);

    // ---- load Q tile once (tf32-rounded) ----
    {
        const float* Qg = g_Q + ((size_t)(b * S_ + q0) * NH_ + h) * HD_;
        #pragma unroll
        for (int i = 0; i < 16; i++) {
            int lin = t + i * 128;
            int row = lin >> 5;
            int c4  = (lin & 31) << 2;
            float4 v = *(const float4*)(Qg + (size_t)row * (NH_ * HD_) + c4);
            float4 o = make_float4(f2tf32(v.x), f2tf32(v.y), f2tf32(v.z), f2tf32(v.w));
            *(float4*)&Qs[row * QSTR + c4] = o;
        }
    }

    float m0 = -1e30f, m1 = -1e30f, l0 = 0.f, l1 = 0.f;
    float acc[16][4];
    #pragma unroll
    for (int nt = 0; nt < 16; nt++)
        #pragma unroll
        for (int x = 0; x < 4; x++) acc[nt][x] = 0.f;

    const int gi0 = q0 + w * 16 + r;
    const int gi1 = gi0 + 8;
    const int kb_lo = (q0 >= WIN_) ? ((q0 - WIN_) >> 6) : 0;
    const int kb_hi = qtile;
    const float scale = 0.08838834764831845f;   // 1/sqrt(128)

    for (int kb = kb_lo; kb <= kb_hi; kb++) {
        __syncthreads();
        // ---- load K,V tiles (tf32-rounded) ----
        {
            const float* Kg = g_K + ((size_t)(b * S_ + kb * 64) * NKV_ + kvh) * HD_;
            const float* Vg = g_V + ((size_t)(b * S_ + kb * 64) * NKV_ + kvh) * HD_;
            #pragma unroll
            for (int i = 0; i < 16; i++) {
                int lin = t + i * 128;
                int row = lin >> 5;
                int c4  = (lin & 31) << 2;
                size_t go = (size_t)row * (NKV_ * HD_) + c4;
                float4 kv = *(const float4*)(Kg + go);
                *(float4*)&Ks[row * KSTR + c4] =
                    make_float4(f2tf32(kv.x), f2tf32(kv.y), f2tf32(kv.z), f2tf32(kv.w));
                float4 vv = *(const float4*)(Vg + go);
                *(float4*)&Vs[row * VSTR + c4] =
                    make_float4(f2tf32(vv.x), f2tf32(vv.y), f2tf32(vv.z), f2tf32(vv.w));
            }
        }
        __syncthreads();

        // ---- S = Q @ K^T : per warp 16x64, 8 n-tiles x 16 k-steps ----
        float s[8][4];
        #pragma unroll
        for (int nt = 0; nt < 8; nt++)
            #pragma unroll
            for (int x = 0; x < 4; x++) s[nt][x] = 0.f;

        #pragma unroll
        for (int ks = 0; ks < 16; ks++) {
            const float* qp = Qs + (w * 16 + r) * QSTR + ks * 8 + c;
            unsigned a0 = __float_as_uint(qp[0]);
            unsigned a1 = __float_as_uint(qp[8 * QSTR]);
            unsigned a2 = __float_as_uint(qp[4]);
            unsigned a3 = __float_as_uint(qp[8 * QSTR + 4]);
            #pragma unroll
            for (int nt = 0; nt < 8; nt++) {
                const float* kp = Ks + (nt * 8 + r) * KSTR + ks * 8 + c;
                mma_tf32(s[nt], a0, a1, a2, a3,
                         __float_as_uint(kp[0]), __float_as_uint(kp[4]));
            }
        }

        // ---- scale + window mask + row max ----
        float mx0 = -1e30f, mx1 = -1e30f;
        #pragma unroll
        for (int nt = 0; nt < 8; nt++) {
            #pragma unroll
            for (int jj = 0; jj < 2; jj++) {
                int gj = kb * 64 + nt * 8 + 2 * c + jj;
                float v0 = s[nt][jj] * scale;
                v0 = (gj <= gi0 && gj + WIN_ >= gi0) ? v0 : -1e30f;
                s[nt][jj] = v0;
                mx0 = fmaxf(mx0, v0);
                float v1 = s[nt][2 + jj] * scale;
                v1 = (gj <= gi1 && gj + WIN_ >= gi1) ? v1 : -1e30f;
                s[nt][2 + jj] = v1;
                mx1 = fmaxf(mx1, v1);
            }
        }
        mx0 = fmaxf(mx0, __shfl_xor_sync(0xffffffffu, mx0, 1));
        mx0 = fmaxf(mx0, __shfl_xor_sync(0xffffffffu, mx0, 2));
        mx1 = fmaxf(mx1, __shfl_xor_sync(0xffffffffu, mx1, 1));
        mx1 = fmaxf(mx1, __shfl_xor_sync(0xffffffffu, mx1, 2));

        const float mn0 = fmaxf(m0, mx0);
        const float mn1 = fmaxf(m1, mx1);
        const float al0 = __expf(m0 - mn0);
        const float al1 = __expf(m1 - mn1);
        m0 = mn0; m1 = mn1;
        l0 *= al0; l1 *= al1;
        #pragma unroll
        for (int nt = 0; nt < 16; nt++) {
            acc[nt][0] *= al0; acc[nt][1] *= al0;
            acc[nt][2] *= al1; acc[nt][3] *= al1;
        }

        // ---- exp + tf32-rounded P to per-warp smem ----
        float ss0 = 0.f, ss1 = 0.f;
        #pragma unroll
        for (int nt = 0; nt < 8; nt++) {
            float p0 = f2tf32(__expf(s[nt][0] - mn0));
            float p1 = f2tf32(__expf(s[nt][1] - mn0));
            float p2 = f2tf32(__expf(s[nt][2] - mn1));
            float p3 = f2tf32(__expf(s[nt][3] - mn1));
            ss0 += p0 + p1;
            ss1 += p2 + p3;
            *(float2*)&Psw[r * PSTR + nt * 8 + 2 * c]       = make_float2(p0, p1);
            *(float2*)&Psw[(r + 8) * PSTR + nt * 8 + 2 * c] = make_float2(p2, p3);
        }
        ss0 += __shfl_xor_sync(0xffffffffu, ss0, 1);
        ss0 += __shfl_xor_sync(0xffffffffu, ss0, 2);
        ss1 += __shfl_xor_sync(0xffffffffu, ss1, 1);
        ss1 += __shfl_xor_sync(0xffffffffu, ss1, 2);
        l0 += ss0; l1 += ss1;

        __syncwarp();

        // ---- O += P @ V : 16 n-tiles x 8 k-steps ----
        #pragma unroll
        for (int ks = 0; ks < 8; ks++) {
            const float* pp = Psw + r * PSTR + ks * 8 + c;
            unsigned a0 = __float_as_uint(pp[0]);
            unsigned a1 = __float_as_uint(pp[8 * PSTR]);
            unsigned a2 = __float_as_uint(pp[4]);
            unsigned a3 = __float_as_uint(pp[8 * PSTR + 4]);
            #pragma unroll
            for (int nt = 0; nt < 16; nt++) {
                const float* vp = Vs + (ks * 8 + c) * VSTR + nt * 8 + r;
                mma_tf32(acc[nt], a0, a1, a2, a3,
                         __float_as_uint(vp[0]), __float_as_uint(vp[4 * VSTR]));
            }
        }
    }

    // ---- epilogue ----
    const float il0 = 1.f / l0;
    const float il1 = 1.f / l1;
    float* O0 = g_AO + ((size_t)(b * S_ + gi0) * NH_ + h) * HD_;
    float* O1 = g_AO + ((size_t)(b * S_ + gi1) * NH_ + h) * HD_;
    #pragma unroll
    for (int nt = 0; nt < 16; nt++) {
        int col = nt * 8 + 2 * c;
        *(float2*)(O0 + col) = make_float2(acc[nt][0] * il0, acc[nt][1] * il0);
        *(float2*)(O1 + col) = make_float2(acc[nt][2] * il1, acc[nt][3] * il1);
    }
}

// ---------------------------------------------------------------------------
extern "C" void kernel_launch(void* const* d_in, const int* in_sizes, int n_in,
                              void* d_out, int out_size)
{
    (void)in_sizes; (void)n_in; (void)out_size;
    const float* hidden  = (const float*)d_in[0];
    const int*   pos_ids = (const int*)d_in[2];
    const float* q_w     = (const float*)d_in[3];
    const float* k_w     = (const float*)d_in[4];
    const float* v_w     = (const float*)d_in[5];
    const float* o_w     = (const float*)d_in[6];
    float* out = (float*)d_out;

    float *Qd, *Kd, *Vd, *AOd;
    cudaGetSymbolAddress((void**)&Qd,  g_Q);
    cudaGetSymbolAddress((void**)&Kd,  g_K);
    cudaGetSymbolAddress((void**)&Vd,  g_V);
    cudaGetSymbolAddress((void**)&AOd, g_AO);

    const int gemm_smem = 2 * (ASZ + BSZ) * (int)sizeof(float);
    cudaFuncSetAttribute(tf32_gemm, cudaFuncAttributeMaxDynamicSharedMemorySize, gemm_smem);

    tf32_gemm<<<dim3(NH_ * HD_ / TFBN, MROWS / TFBM), 256, gemm_smem>>>(
        hidden, q_w, Qd, MROWS, NH_ * HD_, HID_);
    tf32_gemm<<<dim3(NKV_ * HD_ / TFBN, MROWS / TFBM), 256, gemm_smem>>>(
        hidden, k_w, Kd, MROWS, NKV_ * HD_, HID_);
    tf32_gemm<<<dim3(NKV_ * HD_ / TFBN, MROWS / TFBM), 256, gemm_smem>>>(
        hidden, v_w, Vd, MROWS, NKV_ * HD_, HID_);

    {
        int total = MROWS * NH_ * 64 + MROWS * NKV_ * 64;
        rope_kernel<<<(total + 255) / 256, 256>>>(pos_ids);
    }

    {
        int smem = 29952 * (int)sizeof(float);  // 119808 B
        cudaFuncSetAttribute(attn_mma_kernel, cudaFuncAttributeMaxDynamicSharedMemorySize, smem);
        attn_mma_kernel<<<dim3(S_ / 64, NH_, B_), 128, smem>>>();
    }

    tf32_gemm<<<dim3(HID_ / TFBN, MROWS / TFBM), 256, gemm_smem>>>(
        AOd, o_w, out, MROWS, HID_, HID_);
}